// round 8
// baseline (speedup 1.0000x reference)
#include <cuda_runtime.h>
#include <stdint.h>

// Problem constants (from reference)
#define GX 352
#define GY 400
#define GZ 1
#define NB 4
#define NSEG (NB * GZ * GY * GX)    // 563200 (divisible by 4)
#define NC 4
#define NP 2000000                  // divisible by 4

// Output layout: [mean: NSEG*NC floats][counts: NSEG floats]
#define OUT_TOTAL (NSEG * (NC + 1)) // 2816000 floats

// Streaming (evict-first) loads so the 64MB point stream does not evict the
// 11.3MB accumulator region from L2.
__device__ __forceinline__ float4 ldcs_f4(const float4* p) {
    float4 v;
    asm volatile("ld.global.cs.v4.f32 {%0,%1,%2,%3}, [%4];"
                 : "=f"(v.x), "=f"(v.y), "=f"(v.z), "=f"(v.w) : "l"(p));
    return v;
}
__device__ __forceinline__ int4 ldcs_i4(const int4* p) {
    int4 v;
    asm volatile("ld.global.cs.v4.s32 {%0,%1,%2,%3}, [%4];"
                 : "=r"(v.x), "=r"(v.y), "=r"(v.z), "=r"(v.w) : "l"(p));
    return v;
}

__device__ __forceinline__ void red_add_v4(float* dst, float4 f) {
    asm volatile("red.global.add.v4.f32 [%0], {%1, %2, %3, %4};"
                 :: "l"(dst), "f"(f.x), "f"(f.y), "f"(f.z), "f"(f.w)
                 : "memory");
}
__device__ __forceinline__ void red_add_1(float* dst) {
    asm volatile("red.global.add.f32 [%0], %1;"
                 :: "l"(dst), "f"(1.0f) : "memory");
}

// ---------------------------------------------------------------------------
// Scatter-add: 4 points per thread. All 8 loads front-batched (MLP=8),
// streaming cache policy, then 8 REDs. GZ == 1 -> seg = (b*GY + y)*GX + x.
// ---------------------------------------------------------------------------
__global__ void __launch_bounds__(256)
scatter_add_kernel(const float4* __restrict__ features,
                   const int4*   __restrict__ coors,
                   float*        __restrict__ sums,     // NSEG*4
                   float*        __restrict__ counts) { // NSEG
    int i = (blockIdx.x * blockDim.x + threadIdx.x) * 4;
    if (i + 3 < NP) {
        int4   c0 = ldcs_i4(coors + i);
        int4   c1 = ldcs_i4(coors + i + 1);
        int4   c2 = ldcs_i4(coors + i + 2);
        int4   c3 = ldcs_i4(coors + i + 3);
        float4 f0 = ldcs_f4(features + i);
        float4 f1 = ldcs_f4(features + i + 1);
        float4 f2 = ldcs_f4(features + i + 2);
        float4 f3 = ldcs_f4(features + i + 3);

        int s0 = (c0.x * GY + c0.z) * GX + c0.w;
        int s1 = (c1.x * GY + c1.z) * GX + c1.w;
        int s2 = (c2.x * GY + c2.z) * GX + c2.w;
        int s3 = (c3.x * GY + c3.z) * GX + c3.w;

        red_add_v4(sums + (size_t)s0 * NC, f0);
        red_add_v4(sums + (size_t)s1 * NC, f1);
        red_add_v4(sums + (size_t)s2 * NC, f2);
        red_add_v4(sums + (size_t)s3 * NC, f3);
        red_add_1(counts + s0);
        red_add_1(counts + s1);
        red_add_1(counts + s2);
        red_add_1(counts + s3);
    } else {
        for (; i < NP; i++) {
            int4   c = ldcs_i4(coors + i);
            float4 f = ldcs_f4(features + i);
            int s = (c.x * GY + c.z) * GX + c.w;
            red_add_v4(sums + (size_t)s * NC, f);
            red_add_1(counts + s);
        }
    }
}

// ---------------------------------------------------------------------------
// Divide: 4 segments per thread. One float4 count load + 4 float4 sum loads,
// all independent (MLP=5). NSEG % 4 == 0 -> no tail.
// ---------------------------------------------------------------------------
__global__ void __launch_bounds__(256)
divide_kernel(float4* __restrict__ sums,            // NSEG float4s
              const float4* __restrict__ counts4) { // NSEG/4 float4s
    int t = blockIdx.x * blockDim.x + threadIdx.x;
    int seg = t * 4;
    if (seg >= NSEG) return;

    float4 cnt = counts4[t];          // counts[seg..seg+3]
    float4 s0 = sums[seg];
    float4 s1 = sums[seg + 1];
    float4 s2 = sums[seg + 2];
    float4 s3 = sums[seg + 3];

    float i0 = 1.0f / fmaxf(cnt.x, 1.0f);
    float i1 = 1.0f / fmaxf(cnt.y, 1.0f);
    float i2 = 1.0f / fmaxf(cnt.z, 1.0f);
    float i3 = 1.0f / fmaxf(cnt.w, 1.0f);

    s0.x *= i0; s0.y *= i0; s0.z *= i0; s0.w *= i0;
    s1.x *= i1; s1.y *= i1; s1.z *= i1; s1.w *= i1;
    s2.x *= i2; s2.y *= i2; s2.z *= i2; s2.w *= i2;
    s3.x *= i3; s3.y *= i3; s3.z *= i3; s3.w *= i3;

    sums[seg]     = s0;
    sums[seg + 1] = s1;
    sums[seg + 2] = s2;
    sums[seg + 3] = s3;
}

// ---------------------------------------------------------------------------
// Launcher
// ---------------------------------------------------------------------------
extern "C" void kernel_launch(void* const* d_in, const int* in_sizes, int n_in,
                              void* d_out, int out_size) {
    const float4* features = (const float4*)d_in[0];  // (NP, 4) fp32
    const int4*   coors    = (const int4*)d_in[1];    // (NP, 4) int32

    float* out    = (float*)d_out;
    float* sums   = out;                 // NSEG*4
    float* counts = out + NSEG * NC;     // NSEG

    // 1. zero the whole output region (graph-capturable memset node)
    cudaMemsetAsync(d_out, 0, (size_t)OUT_TOTAL * sizeof(float));

    // 2. scatter-add points (4 points per thread)
    {
        int threads = 256;
        int work = (NP + 3) / 4;
        int blocks = (work + threads - 1) / threads;
        scatter_add_kernel<<<blocks, threads>>>(features, coors, sums, counts);
    }

    // 3. normalize to mean (4 segments per thread)
    {
        int threads = 256;
        int work = NSEG / 4;
        int blocks = (work + threads - 1) / threads;
        divide_kernel<<<blocks, threads>>>((float4*)sums, (const float4*)counts);
    }
}

// round 9
// speedup vs baseline: 1.1436x; 1.1436x over previous
#include <cuda_runtime.h>
#include <stdint.h>

// Problem constants (from reference)
#define GX 352
#define GY 400
#define GZ 1
#define NB 4
#define NSEG (NB * GZ * GY * GX)    // 563200
#define NC 4
#define NP 2000000

// Output layout: [mean: NSEG*NC floats][counts: NSEG floats]
#define OUT_TOTAL (NSEG * (NC + 1)) // 2816000 floats

// ---------------------------------------------------------------------------
// Persistent scratch accumulator. __device__ globals are zero-initialized at
// module load. The divide kernel restores the all-zeros invariant after
// consuming it, so every graph replay starts from zeros -> deterministic,
// and NO memset pass is needed.
//   [0 .. NSEG*4)          per-segment feature sums (float4 per seg)
//   [NSEG*4 .. NSEG*5)     per-segment counts
// ---------------------------------------------------------------------------
__device__ float g_scratch[NSEG * (NC + 1)];

__device__ __forceinline__ void red_add_v4(float* dst, float4 f) {
    asm volatile("red.global.add.v4.f32 [%0], {%1, %2, %3, %4};"
                 :: "l"(dst), "f"(f.x), "f"(f.y), "f"(f.z), "f"(f.w)
                 : "memory");
}
__device__ __forceinline__ void red_add_1(float* dst) {
    asm volatile("red.global.add.f32 [%0], %1;"
                 :: "l"(dst), "f"(1.0f) : "memory");
}

// ---------------------------------------------------------------------------
// Scatter-add: one point per thread (best-measured config).
// GZ == 1 -> seg = (b*GY + y)*GX + x.
// ---------------------------------------------------------------------------
__global__ void __launch_bounds__(256)
scatter_add_kernel(const float4* __restrict__ features,
                   const int4*   __restrict__ coors) {
    int i = blockIdx.x * blockDim.x + threadIdx.x;
    if (i >= NP) return;

    int4   c = coors[i];                       // (b, z, y, x)
    float4 f = features[i];
    int seg = (c.x * GY + c.z) * GX + c.w;

    red_add_v4(g_scratch + (size_t)seg * NC, f);
    red_add_1(g_scratch + NSEG * NC + seg);
}

// ---------------------------------------------------------------------------
// Divide + emit + scratch-restore: one segment per thread.
//  - read sums (float4) and count from scratch
//  - write mean (float4) and count to d_out
//  - zero the scratch entries back (restores invariant for next replay)
// ---------------------------------------------------------------------------
__global__ void __launch_bounds__(256)
divide_kernel(float* __restrict__ out) {
    int seg = blockIdx.x * blockDim.x + threadIdx.x;
    if (seg >= NSEG) return;

    float4* s_sums   = (float4*)g_scratch;
    float*  s_counts = g_scratch + NSEG * NC;

    float4 s   = s_sums[seg];
    float  cnt = s_counts[seg];

    float inv = 1.0f / fmaxf(cnt, 1.0f);
    float4 m;
    m.x = s.x * inv; m.y = s.y * inv; m.z = s.z * inv; m.w = s.w * inv;

    ((float4*)out)[seg]       = m;    // mean region
    out[NSEG * NC + seg]      = cnt;  // counts region

    // restore scratch to zero for the next graph replay
    s_sums[seg]   = make_float4(0.f, 0.f, 0.f, 0.f);
    s_counts[seg] = 0.0f;
}

// ---------------------------------------------------------------------------
// Launcher: just two kernels, no memset node.
// ---------------------------------------------------------------------------
extern "C" void kernel_launch(void* const* d_in, const int* in_sizes, int n_in,
                              void* d_out, int out_size) {
    const float4* features = (const float4*)d_in[0];  // (NP, 4) fp32
    const int4*   coors    = (const int4*)d_in[1];    // (NP, 4) int32
    float* out = (float*)d_out;

    {
        int threads = 256;
        int blocks = (NP + threads - 1) / threads;
        scatter_add_kernel<<<blocks, threads>>>(features, coors);
    }
    {
        int threads = 256;
        int blocks = (NSEG + threads - 1) / threads;
        divide_kernel<<<blocks, threads>>>(out);
    }
}

// round 10
// speedup vs baseline: 1.1524x; 1.0077x over previous
#include <cuda_runtime.h>
#include <stdint.h>

// Problem constants (from reference)
#define GX 352
#define GY 400
#define GZ 1
#define NB 4
#define NSEG (NB * GZ * GY * GX)    // 563200 (even)
#define NC 4
#define NP 2000000

// Output layout: [mean: NSEG*NC floats][counts: NSEG floats]
#define OUT_TOTAL (NSEG * (NC + 1)) // 2816000 floats

// ---------------------------------------------------------------------------
// Persistent scratch accumulator. Zero-initialized at module load; the divide
// kernel restores the all-zeros invariant after consuming it, so every graph
// replay starts from zeros -> deterministic, and NO memset pass is needed.
//   [0 .. NSEG*4)          per-segment feature sums (float4 per seg)
//   [NSEG*4 .. NSEG*5)     per-segment counts
// ---------------------------------------------------------------------------
__device__ float g_scratch[NSEG * (NC + 1)];

__device__ __forceinline__ void red_add_v4(float* dst, float4 f) {
    asm volatile("red.global.add.v4.f32 [%0], {%1, %2, %3, %4};"
                 :: "l"(dst), "f"(f.x), "f"(f.y), "f"(f.z), "f"(f.w)
                 : "memory");
}
__device__ __forceinline__ void red_add_1(float* dst) {
    asm volatile("red.global.add.f32 [%0], %1;"
                 :: "l"(dst), "f"(1.0f) : "memory");
}

// ---------------------------------------------------------------------------
// Scatter-add: one point per thread (measured best config; at REDG floor).
// GZ == 1 -> seg = (b*GY + y)*GX + x.
// ---------------------------------------------------------------------------
__global__ void __launch_bounds__(256)
scatter_add_kernel(const float4* __restrict__ features,
                   const int4*   __restrict__ coors) {
    int i = blockIdx.x * blockDim.x + threadIdx.x;
    if (i >= NP) return;

    int4   c = coors[i];                       // (b, z, y, x)
    float4 f = features[i];
    int seg = (c.x * GY + c.z) * GX + c.w;

    red_add_v4(g_scratch + (size_t)seg * NC, f);
    red_add_1(g_scratch + NSEG * NC + seg);
}

// ---------------------------------------------------------------------------
// Divide + emit + scratch-restore: TWO segments per thread.
//  - front-batch: 2 float4 sum loads + 1 float2 count load (MLP=3)
//  - write 2 float4 means + 1 float2 count pair to d_out
//  - zero scratch back (2 float4 + 1 float2 stores)
// NSEG is even -> no tail. seg is even -> float2 accesses 8B-aligned.
// ---------------------------------------------------------------------------
__global__ void __launch_bounds__(256)
divide_kernel(float* __restrict__ out) {
    int t = blockIdx.x * blockDim.x + threadIdx.x;
    int seg = t * 2;
    if (seg >= NSEG) return;

    float4* s_sums    = (float4*)g_scratch;
    float2* s_counts2 = (float2*)(g_scratch + NSEG * NC);

    // front-batched independent loads
    float4 s0  = s_sums[seg];
    float4 s1  = s_sums[seg + 1];
    float2 cnt = s_counts2[t];

    float i0 = 1.0f / fmaxf(cnt.x, 1.0f);
    float i1 = 1.0f / fmaxf(cnt.y, 1.0f);

    float4 m0, m1;
    m0.x = s0.x * i0; m0.y = s0.y * i0; m0.z = s0.z * i0; m0.w = s0.w * i0;
    m1.x = s1.x * i1; m1.y = s1.y * i1; m1.z = s1.z * i1; m1.w = s1.w * i1;

    float4* out_mean    = (float4*)out;
    float2* out_counts2 = (float2*)(out + NSEG * NC);

    out_mean[seg]     = m0;
    out_mean[seg + 1] = m1;
    out_counts2[t]    = cnt;

    // restore scratch to zero for the next graph replay
    s_sums[seg]     = make_float4(0.f, 0.f, 0.f, 0.f);
    s_sums[seg + 1] = make_float4(0.f, 0.f, 0.f, 0.f);
    s_counts2[t]    = make_float2(0.f, 0.f);
}

// ---------------------------------------------------------------------------
// Launcher: two kernels, no memset node.
// ---------------------------------------------------------------------------
extern "C" void kernel_launch(void* const* d_in, const int* in_sizes, int n_in,
                              void* d_out, int out_size) {
    const float4* features = (const float4*)d_in[0];  // (NP, 4) fp32
    const int4*   coors    = (const int4*)d_in[1];    // (NP, 4) int32
    float* out = (float*)d_out;

    {
        int threads = 256;
        int blocks = (NP + threads - 1) / threads;
        scatter_add_kernel<<<blocks, threads>>>(features, coors);
    }
    {
        int threads = 256;
        int work = NSEG / 2;
        int blocks = (work + threads - 1) / threads;
        divide_kernel<<<blocks, threads>>>(out);
    }
}